// round 5
// baseline (speedup 1.0000x reference)
#include <cuda_runtime.h>
#include <stdint.h>
#include <float.h>

// ChamferLoss2D: N=16, P=4096, D=2.
// cost_n = 0.5*(mean_i min_j C + mean_j min_i C), C = sqrt(clip(|x-y|^2, EPS))
// out = mean_n cost_n * (sum(set2_n) >= 0)
//
// Grid-based exact NN. Query kernel is two-phase:
//   fast path: per-lane 3x3 cell box + exact lower-bound stop test
//   slow path: __ballot unsatisfied lanes; whole warp cooperatively expands
//              rings for each one (kills tail-query divergence drag).
// Lower bound treats domain-clamped sides as infinite (edge cells absorb all
// outliers), so edge queries terminate immediately; full grid coverage makes
// lb = inf and terminates too => exact for ANY input.

#define N_BATCH 16
#define P 4096
#define TPB 256

#define G 96
#define CELLS (G * G)            // 9216
#define CPT (CELLS / TPB)        // 36
#define PPT (P / TPB)            // 16

#define DOM_LO (-5.2f)
#define DOM_W  (10.4f)
#define CELL_W (DOM_W / (float)G)
#define INV_W  ((float)G / DOM_W)

#define EPS 1e-12f
#define OUT_WT (0.5f / (float)P / (float)N_BATCH)

__device__ float2   g_pts[2][N_BATCH][P];               // cell-sorted points
__device__ uint16_t g_cellstart[2][N_BATCH][CELLS + 1]; // P=4096 fits u16
__device__ float    g_mask[N_BATCH];

__device__ __forceinline__ int cell_coord(float v) {
    int c = (int)((v - DOM_LO) * INV_W);
    return min(max(c, 0), G - 1);
}

// ---- build: one block per (set, batch): histogram -> scan -> scatter --------
__global__ void __launch_bounds__(TPB) build_kernel(
    const float* __restrict__ s1, const float* __restrict__ s2,
    float* __restrict__ out) {
    const int set = blockIdx.x >> 4;
    const int n   = blockIdx.x & 15;
    const float2* __restrict__ src =
        (const float2*)((set ? s2 : s1) + (size_t)n * P * 2);

    __shared__ uint32_t s_cnt[CELLS];
    __shared__ uint32_t s_wsum[TPB / 32];
    __shared__ float    s_red[TPB / 32];

    const int t = threadIdx.x;
    const int lane = t & 31, w = t >> 5;

#pragma unroll
    for (int k = 0; k < CPT; k++) s_cnt[k * TPB + t] = 0;
    __syncthreads();

    float2 pt[PPT];
    int    cid[PPT];
    float  msum = 0.0f;
#pragma unroll
    for (int k = 0; k < PPT; k++) {
        float2 p = src[k * TPB + t];
        pt[k] = p;
        cid[k] = cell_coord(p.y) * G + cell_coord(p.x);
        atomicAdd(&s_cnt[cid[k]], 1u);
        msum += p.x + p.y;
    }
    __syncthreads();

    // Exclusive scan over CELLS (thread owns a contiguous CPT run).
    uint32_t tot = 0;
#pragma unroll
    for (int c = 0; c < CPT; c++) tot += s_cnt[t * CPT + c];
    uint32_t inc = tot;
#pragma unroll
    for (int o = 1; o < 32; o <<= 1) {
        uint32_t v = __shfl_up_sync(0xffffffffu, inc, o);
        if (lane >= o) inc += v;
    }
    if (lane == 31) s_wsum[w] = inc;
    uint32_t excl = inc - tot;
    __syncthreads();
    uint32_t wbase = 0;
#pragma unroll
    for (int ww = 0; ww < TPB / 32; ww++) {
        uint32_t v = s_wsum[ww];
        if (ww < w) wbase += v;
    }
    uint32_t run = wbase + excl;
#pragma unroll
    for (int c = 0; c < CPT; c++) {
        uint32_t v = s_cnt[t * CPT + c];
        s_cnt[t * CPT + c] = run;
        run += v;
    }
    __syncthreads();

    uint16_t* __restrict__ gs = g_cellstart[set][n];
#pragma unroll
    for (int k = 0; k < CPT; k++) gs[k * TPB + t] = (uint16_t)s_cnt[k * TPB + t];
    if (t == 0) gs[CELLS] = (uint16_t)P;  // P=4096 fits (max index used as bound)
    __syncthreads();

    float2* __restrict__ gp = g_pts[set][n];
#pragma unroll
    for (int k = 0; k < PPT; k++) {
        uint32_t pos = atomicAdd(&s_cnt[cid[k]], 1u);
        gp[pos] = pt[k];
    }

#pragma unroll
    for (int o = 16; o > 0; o >>= 1) msum += __shfl_down_sync(0xffffffffu, msum, o);
    if (lane == 0) s_red[w] = msum;
    __syncthreads();
    if (t == 0) {
        float a = 0.0f;
#pragma unroll
        for (int ww = 0; ww < TPB / 32; ww++) a += s_red[ww];
        if (set == 1) g_mask[n] = (a >= 0.0f) ? 1.0f : 0.0f;
        if (set == 0 && n == 0) out[0] = 0.0f;
    }
}

// ---- query ------------------------------------------------------------------
__device__ __forceinline__ void scan_run(
    const float2* __restrict__ pts, uint32_t s, uint32_t e,
    float qx, float qy, float& best) {
    for (uint32_t idx = s; idx < e; idx++) {
        float2 p = pts[idx];
        float dx = qx - p.x;
        float dy = qy - p.y;
        best = fminf(best, fmaf(dx, dx, dy * dy));
    }
}

// Lower bound to the unscanned region outside box radius r around (cx,cy).
// Clamped sides (box reaches grid edge) => FLT_MAX (edge cells hold all
// outliers on that side, already scanned).
__device__ __forceinline__ float box_lb(float qx, float qy, int cx, int cy, int r) {
    float l = (cx - r <= 0)     ? FLT_MAX : qx - (DOM_LO + (float)(cx - r) * CELL_W);
    float rt = (cx + r >= G - 1) ? FLT_MAX : (DOM_LO + (float)(cx + r + 1) * CELL_W) - qx;
    float b = (cy - r <= 0)     ? FLT_MAX : qy - (DOM_LO + (float)(cy - r) * CELL_W);
    float tp = (cy + r >= G - 1) ? FLT_MAX : (DOM_LO + (float)(cy + r + 1) * CELL_W) - qy;
    return fminf(fminf(l, rt), fminf(b, tp));
}

__global__ void __launch_bounds__(TPB) query_kernel(float* __restrict__ out) {
    // blockIdx: [dir(2)][n(16)][chunk(16)]
    const int chunk = blockIdx.x & 15;
    const int n     = (blockIdx.x >> 4) & 15;
    const int dir   = blockIdx.x >> 8;
    const int dst   = 1 - dir;
    const int t     = threadIdx.x;
    const int lane  = t & 31;

    const float2 q = g_pts[dir][n][chunk * TPB + t];
    const float2*   __restrict__ pts = g_pts[dst][n];
    const uint16_t* __restrict__ cs  = g_cellstart[dst][n];

    const int cx = cell_coord(q.x);
    const int cy = cell_coord(q.y);

    float best = FLT_MAX;

    // ---- fast path: 3x3 box, row-run scans ----
    {
        int ilo = max(cx - 1, 0), ihi = min(cx + 1, G - 1);
        int jlo = max(cy - 1, 0), jhi = min(cy + 1, G - 1);
        for (int j = jlo; j <= jhi; j++)
            scan_run(pts, cs[j * G + ilo], cs[j * G + ihi + 1], q.x, q.y, best);
    }
    float lb1 = box_lb(q.x, q.y, cx, cy, 1);
    bool need = best > lb1 * lb1;   // lb1==FLT_MAX -> lb1^2=inf -> satisfied

    // ---- slow path: cooperative ring expansion per flagged lane ----
    unsigned needmask = __ballot_sync(0xffffffffu, need);
    while (needmask) {
        const int tgt = __ffs(needmask) - 1;
        needmask &= needmask - 1;
        const float qx = __shfl_sync(0xffffffffu, q.x, tgt);
        const float qy = __shfl_sync(0xffffffffu, q.y, tgt);
        const int  qcx = __shfl_sync(0xffffffffu, cx, tgt);
        const int  qcy = __shfl_sync(0xffffffffu, cy, tgt);
        float b = __shfl_sync(0xffffffffu, best, tgt);

        int r = 1;
        while (true) {
            float lb = box_lb(qx, qy, qcx, qcy, r);
            if (b <= lb * lb) break;   // also breaks on full coverage (inf)
            r++;
            float bl = FLT_MAX;
            const int ringn = 8 * r;
            for (int base = 0; base < ringn; base += 32) {
                int idx = base + lane;
                if (idx < ringn) {
                    int side = idx / (2 * r), i = idx % (2 * r);
                    int gx, gy;
                    if (side == 0)      { gx = qcx - r + i; gy = qcy - r; }
                    else if (side == 1) { gx = qcx + r;     gy = qcy - r + i; }
                    else if (side == 2) { gx = qcx + r - i; gy = qcy + r; }
                    else                { gx = qcx - r;     gy = qcy + r - i; }
                    if (gx >= 0 && gx < G && gy >= 0 && gy < G) {
                        int c = gy * G + gx;
                        scan_run(pts, cs[c], cs[c + 1], qx, qy, bl);
                    }
                }
            }
#pragma unroll
            for (int o = 16; o > 0; o >>= 1)
                bl = fminf(bl, __shfl_xor_sync(0xffffffffu, bl, o));
            b = fminf(b, bl);
        }
        if (lane == tgt) best = b;
    }

    float d = sqrtf(fmaxf(best, EPS));

    // Block reduce (all threads in block share (dir, n)).
#pragma unroll
    for (int o = 16; o > 0; o >>= 1) d += __shfl_down_sync(0xffffffffu, d, o);
    __shared__ float s_red[TPB / 32];
    if (lane == 0) s_red[t >> 5] = d;
    __syncthreads();
    if (t == 0) {
        float a = 0.0f;
#pragma unroll
        for (int ww = 0; ww < TPB / 32; ww++) a += s_red[ww];
        atomicAdd(out, a * g_mask[n] * OUT_WT);
    }
}

extern "C" void kernel_launch(void* const* d_in, const int* in_sizes, int n_in,
                              void* d_out, int out_size) {
    const float* s1 = (const float*)d_in[0];  // point_set_1: [16,4096,2] f32
    const float* s2 = (const float*)d_in[1];  // point_set_2: [16,4096,2] f32
    float* out = (float*)d_out;

    build_kernel<<<2 * N_BATCH, TPB>>>(s1, s2, out);
    query_kernel<<<2 * N_BATCH * (P / TPB), TPB>>>(out);
}

// round 7
// speedup vs baseline: 1.7509x; 1.7509x over previous
#include <cuda_runtime.h>
#include <stdint.h>
#include <float.h>

// ChamferLoss2D: N=16, P=4096, D=2.
// cost_n = 0.5*(mean_i min_j C + mean_j min_i C), C = sqrt(clip(|x-y|^2, EPS))
// out = mean_n cost_n * (sum(set2_n) >= 0)
//
// Grid NN, exact. Query kernel copies the ENTIRE destination structure
// (sorted points 32KB + u16 cell table 12.8KB) into shared memory, so the
// dependent search chains run at LDS latency (29cy) instead of L2 (250cy).
// Per-lane 3x3 fast path + per-lane ring expansion with edge-aware lower
// bound (domain-clamped sides => inf; exact for ANY input).

#define N_BATCH 16
#define P 4096

#define G 80
#define CELLS (G * G)            // 6400
#define CS_PAD (CELLS + 2)       // 6402 entries -> 4B-aligned row stride

#define DOM_LO (-5.2f)
#define DOM_W  (10.4f)
#define CELL_W (DOM_W / (float)G)
#define INV_W  ((float)G / DOM_W)

#define EPS 1e-12f
#define OUT_WT (0.5f / (float)P / (float)N_BATCH)

__device__ float2   g_pts[2][N_BATCH][P];           // cell-sorted points
__device__ uint16_t g_cellstart[2][N_BATCH][CS_PAD];
__device__ float    g_mask[N_BATCH];

__device__ __forceinline__ int cell_coord(float v) {
    int c = (int)((v - DOM_LO) * INV_W);
    return min(max(c, 0), G - 1);
}

// ---- build: one block of 512 per (set, batch) -------------------------------
#define TPB_B 512
#define PPT_B (P / TPB_B)        // 8
#define CELLS_PADB 6656          // 512 * 13
#define CPT_B 13

__global__ void __launch_bounds__(TPB_B) build_kernel(
    const float* __restrict__ s1, const float* __restrict__ s2,
    float* __restrict__ out) {
    const int set = blockIdx.x >> 4;
    const int n   = blockIdx.x & 15;
    const float2* __restrict__ src =
        (const float2*)((set ? s2 : s1) + (size_t)n * P * 2);

    __shared__ uint32_t s_cnt[CELLS_PADB];
    __shared__ uint32_t s_wsum[TPB_B / 32];
    __shared__ float    s_red[TPB_B / 32];

    const int t = threadIdx.x;
    const int lane = t & 31, w = t >> 5;

#pragma unroll
    for (int k = 0; k < CPT_B; k++) s_cnt[k * TPB_B + t] = 0;
    __syncthreads();

    float2 pt[PPT_B];
    int    cid[PPT_B];
    float  msum = 0.0f;
#pragma unroll
    for (int k = 0; k < PPT_B; k++) {
        float2 p = src[k * TPB_B + t];
        pt[k] = p;
        cid[k] = cell_coord(p.y) * G + cell_coord(p.x);
        atomicAdd(&s_cnt[cid[k]], 1u);
        msum += p.x + p.y;
    }
    __syncthreads();

    // Exclusive scan over padded cells (thread owns contiguous CPT_B run).
    uint32_t tot = 0;
#pragma unroll
    for (int c = 0; c < CPT_B; c++) tot += s_cnt[t * CPT_B + c];
    uint32_t inc = tot;
#pragma unroll
    for (int o = 1; o < 32; o <<= 1) {
        uint32_t v = __shfl_up_sync(0xffffffffu, inc, o);
        if (lane >= o) inc += v;
    }
    if (lane == 31) s_wsum[w] = inc;
    uint32_t excl = inc - tot;
    __syncthreads();
    uint32_t wbase = 0;
#pragma unroll
    for (int ww = 0; ww < TPB_B / 32; ww++) {
        uint32_t v = s_wsum[ww];
        if (ww < w) wbase += v;
    }
    uint32_t run = wbase + excl;
#pragma unroll
    for (int c = 0; c < CPT_B; c++) {
        uint32_t v = s_cnt[t * CPT_B + c];
        s_cnt[t * CPT_B + c] = run;
        run += v;
    }
    __syncthreads();

    // Publish cell starts (s_cnt[CELLS] == P thanks to zero padding cells).
    uint16_t* __restrict__ gs = g_cellstart[set][n];
#pragma unroll
    for (int k = 0; k < CPT_B; k++) {
        int i = k * TPB_B + t;
        if (i < CS_PAD) gs[i] = (uint16_t)s_cnt[i];
    }
    __syncthreads();  // publish reads s_cnt before scatter mutates it

    float2* __restrict__ gp = g_pts[set][n];
#pragma unroll
    for (int k = 0; k < PPT_B; k++) {
        uint32_t pos = atomicAdd(&s_cnt[cid[k]], 1u);
        gp[pos] = pt[k];
    }

#pragma unroll
    for (int o = 16; o > 0; o >>= 1) msum += __shfl_down_sync(0xffffffffu, msum, o);
    if (lane == 0) s_red[w] = msum;
    __syncthreads();
    if (t == 0) {
        float a = 0.0f;
#pragma unroll
        for (int ww = 0; ww < TPB_B / 32; ww++) a += s_red[ww];
        if (set == 1) g_mask[n] = (a >= 0.0f) ? 1.0f : 0.0f;
        if (set == 0 && n == 0) out[0] = 0.0f;
    }
}

// ---- query ------------------------------------------------------------------
#define TPB 256

__device__ __forceinline__ void scan_run(
    const float2* pts, int s, int e, float qx, float qy, float& best) {
    for (int idx = s; idx < e; idx++) {
        float2 p = pts[idx];
        float dx = qx - p.x;
        float dy = qy - p.y;
        best = fminf(best, fmaf(dx, dx, dy * dy));
    }
}

// Lower bound to unscanned region outside box radius r; clamped sides => inf.
__device__ __forceinline__ float box_lb(float qx, float qy, int cx, int cy, int r) {
    float l  = (cx - r <= 0)     ? FLT_MAX : qx - (DOM_LO + (float)(cx - r) * CELL_W);
    float rt = (cx + r >= G - 1) ? FLT_MAX : (DOM_LO + (float)(cx + r + 1) * CELL_W) - qx;
    float b  = (cy - r <= 0)     ? FLT_MAX : qy - (DOM_LO + (float)(cy - r) * CELL_W);
    float tp = (cy + r >= G - 1) ? FLT_MAX : (DOM_LO + (float)(cy + r + 1) * CELL_W) - qy;
    return fminf(fminf(l, rt), fminf(b, tp));
}

__global__ void __launch_bounds__(TPB) query_kernel(float* __restrict__ out) {
    // blockIdx: [dir(2)][n(16)][chunk(16)]
    const int chunk = blockIdx.x & 15;
    const int n     = (blockIdx.x >> 4) & 15;
    const int dir   = blockIdx.x >> 8;
    const int dst   = 1 - dir;
    const int t     = threadIdx.x;
    const int lane  = t & 31;

    __shared__ __align__(16) float2   s_pts[P];       // 32 KB
    __shared__ __align__(4)  uint16_t s_cs[CS_PAD];   // 12.8 KB
    __shared__ float s_red[TPB / 32];

    // Copy destination structure into smem (all L2 hits, coalesced).
    {
        const float4* gp4 = (const float4*)g_pts[dst][n];
        float4* sp4 = (float4*)s_pts;
#pragma unroll
        for (int k = 0; k < (P / 2) / TPB; k++)       // 2048 float4
            sp4[k * TPB + t] = gp4[k * TPB + t];
        const uint32_t* gc = (const uint32_t*)g_cellstart[dst][n];
        uint32_t* sc = (uint32_t*)s_cs;
        for (int i = t; i < CS_PAD / 2; i += TPB)     // 3201 u32
            sc[i] = gc[i];
    }

    const float2 q = g_pts[dir][n][chunk * TPB + t];
    const int cx = cell_coord(q.x);
    const int cy = cell_coord(q.y);

    __syncthreads();

    float best = FLT_MAX;

    // Fast path: 3x3 box as three contiguous row-runs.
    {
        int ilo = max(cx - 1, 0), ihi = min(cx + 1, G - 1);
        int jlo = max(cy - 1, 0), jhi = min(cy + 1, G - 1);
        for (int j = jlo; j <= jhi; j++)
            scan_run(s_pts, s_cs[j * G + ilo], s_cs[j * G + ihi + 1], q.x, q.y, best);
    }

    // Per-lane ring expansion (smem-resident, 29cy chains).
    int r = 1;
    while (true) {
        float lb = box_lb(q.x, q.y, cx, cy, r);
        if (best <= lb * lb) break;       // inf^2 covers clamped/full coverage
        r++;
        int ilo = max(cx - r, 0), ihi = min(cx + r, G - 1);
        int jt = cy - r, jb = cy + r;
        if (jt >= 0)
            scan_run(s_pts, s_cs[jt * G + ilo], s_cs[jt * G + ihi + 1], q.x, q.y, best);
        if (jb <= G - 1)
            scan_run(s_pts, s_cs[jb * G + ilo], s_cs[jb * G + ihi + 1], q.x, q.y, best);
        int jlo2 = max(cy - r + 1, 0), jhi2 = min(cy + r - 1, G - 1);
        for (int j = jlo2; j <= jhi2; j++) {
            if (cx - r >= 0) {
                int c = j * G + (cx - r);
                scan_run(s_pts, s_cs[c], s_cs[c + 1], q.x, q.y, best);
            }
            if (cx + r <= G - 1) {
                int c = j * G + (cx + r);
                scan_run(s_pts, s_cs[c], s_cs[c + 1], q.x, q.y, best);
            }
        }
    }

    float d = sqrtf(fmaxf(best, EPS));

    // Block reduce (all threads in block share (dir, n)).
#pragma unroll
    for (int o = 16; o > 0; o >>= 1) d += __shfl_down_sync(0xffffffffu, d, o);
    if (lane == 0) s_red[t >> 5] = d;
    __syncthreads();
    if (t == 0) {
        float a = 0.0f;
#pragma unroll
        for (int ww = 0; ww < TPB / 32; ww++) a += s_red[ww];
        atomicAdd(out, a * g_mask[n] * OUT_WT);
    }
}

extern "C" void kernel_launch(void* const* d_in, const int* in_sizes, int n_in,
                              void* d_out, int out_size) {
    const float* s1 = (const float*)d_in[0];  // point_set_1: [16,4096,2] f32
    const float* s2 = (const float*)d_in[1];  // point_set_2: [16,4096,2] f32
    float* out = (float*)d_out;

    build_kernel<<<2 * N_BATCH, TPB_B>>>(s1, s2, out);
    query_kernel<<<2 * N_BATCH * (P / TPB), TPB>>>(out);
}